// round 5
// baseline (speedup 1.0000x reference)
#include <cuda_runtime.h>
#include <cuda_bf16.h>
#include <math.h>
#include <stdint.h>

#define KC 19
#define MP 10
#define CH 720
#define CHP 768
#define JN 190
#define JP 192
#define NMAX 65536

// ---------------- scratch ----------------
__device__ __align__(256) __nv_bfloat16 g_Bhi[JP * CHP];
__device__ __align__(256) __nv_bfloat16 g_Blo[JP * CHP];
__device__ float g_mu[NMAX];
__device__ float g_P[NMAX];
__device__ float g_Q[NMAX];
__device__ float g_e[(size_t)NMAX * MP];
__device__ float g_c[NMAX];
__device__ int   g_cnt[KC];
__device__ float g_T3[3][JN];   // [0]=E (raw per-class sums), [1]=T2acc, [2]=T3acc

// ---------------- helpers ----------------
__device__ __forceinline__ uint32_t smem_u32(const void* p) {
    uint32_t a;
    asm("{ .reg .u64 t; cvta.to.shared.u64 t, %1; cvt.u32.u64 %0, t; }" : "=r"(a) : "l"(p));
    return a;
}
__device__ __forceinline__ float warpReduceSum(float v) {
    #pragma unroll
    for (int o = 16; o > 0; o >>= 1) v += __shfl_xor_sync(0xffffffffu, v, o);
    return v;
}
__device__ __forceinline__ float blockReduceSum(float v, float* sh) {
    __syncthreads();
    v = warpReduceSum(v);
    int lane = threadIdx.x & 31, w = threadIdx.x >> 5;
    if (lane == 0) sh[w] = v;
    __syncthreads();
    int nw = (blockDim.x + 31) >> 5;
    v = (threadIdx.x < nw) ? sh[threadIdx.x] : 0.f;
    if (w == 0) { v = warpReduceSum(v); if (lane == 0) sh[0] = v; }
    __syncthreads();
    return sh[0];
}
__device__ __forceinline__ void split2p(float a0, float a1, unsigned& h, unsigned& l) {
    unsigned hp;
    asm("cvt.rn.bf16x2.f32 %0, %1, %2;" : "=r"(hp) : "f"(a1), "f"(a0));
    float h0 = __uint_as_float(hp << 16);
    float h1 = __uint_as_float(hp & 0xffff0000u);
    unsigned lp;
    asm("cvt.rn.bf16x2.f32 %0, %1, %2;" : "=r"(lp) : "f"(a1 - h1), "f"(a0 - h0));
    h = hp; l = lp;
}

#define LDMX4(r0, r1, r2, r3, addr) \
    asm volatile("ldmatrix.sync.aligned.m8n8.x4.shared.b16 {%0,%1,%2,%3}, [%4];" \
                 : "=r"(r0), "=r"(r1), "=r"(r2), "=r"(r3) : "r"(addr))

#define MMA16816(d, a, b0, b1) \
    asm volatile("mma.sync.aligned.m16n8k16.row.col.f32.bf16.bf16.f32 " \
                 "{%0,%1,%2,%3}, {%4,%5,%6,%7}, {%8,%9}, {%0,%1,%2,%3};" \
                 : "+f"((d)[0]), "+f"((d)[1]), "+f"((d)[2]), "+f"((d)[3]) \
                 : "r"((a)[0]), "r"((a)[1]), "r"((a)[2]), "r"((a)[3]), "r"(b0), "r"(b1))

#define CP_ASYNC16(dst, src) \
    asm volatile("cp.async.ca.shared.global [%0], [%1], 16;" \
                 :: "r"(dst), "l"(src) : "memory")

// ---------------- K0: warp-per-row stats ----------------
__global__ __launch_bounds__(256) void kstats(const float* __restrict__ x,
                                              const float* __restrict__ gamma,
                                              const float* __restrict__ beta, int N) {
    int warp = threadIdx.x >> 5, lane = threadIdx.x & 31;
    int n = blockIdx.x * 8 + warp;
    if (n >= N) return;
    const float4* xr = (const float4*)(x + (size_t)n * CH);
    float4 v[6];
    float s = 0.f, sq = 0.f;
    #pragma unroll
    for (int i = 0; i < 6; i++) {
        int idx = i * 32 + lane;
        if (idx < 180) {
            v[i] = xr[idx];
            s += v[i].x + v[i].y + v[i].z + v[i].w;
            sq += v[i].x * v[i].x + v[i].y * v[i].y + v[i].z * v[i].z + v[i].w * v[i].w;
        } else v[i] = make_float4(0, 0, 0, 0);
    }
    s = warpReduceSum(s);
    sq = warpReduceSum(sq);
    float mu = s * (1.f / (float)CH);
    float rs = rsqrtf(sq * (1.f / (float)CH) - mu * mu + 1e-5f);
    float yn = 0.f;
    #pragma unroll
    for (int i = 0; i < 6; i++) {
        int idx = i * 32 + lane;
        if (idx < 180) {
            float4 g4 = ((const float4*)gamma)[idx];
            float4 b4 = ((const float4*)beta)[idx];
            float a = (v[i].x - mu) * rs * g4.x + b4.x;
            float b = (v[i].y - mu) * rs * g4.y + b4.y;
            float c = (v[i].z - mu) * rs * g4.z + b4.z;
            float d = (v[i].w - mu) * rs * g4.w + b4.w;
            yn += a * a + b * b + c * c + d * d;
        }
    }
    yn = warpReduceSum(yn);
    float inv = 1.f / fmaxf(sqrtf(yn), 1e-12f);
    if (lane == 0) { g_mu[n] = mu; g_P[n] = rs * inv; g_Q[n] = inv; }
}

// ---------------- K1: normalize prototypes + init ----------------
__global__ __launch_bounds__(192) void kprotoB(const float* __restrict__ proto) {
    int p = blockIdx.x;
    int t = threadIdx.x;
    __shared__ float sh[32];
    if (p == JN) {
        ((uint2*)(g_Bhi + (size_t)190 * CHP))[t] = make_uint2(0u, 0u);
        ((uint2*)(g_Bhi + (size_t)191 * CHP))[t] = make_uint2(0u, 0u);
        ((uint2*)(g_Blo + (size_t)190 * CHP))[t] = make_uint2(0u, 0u);
        ((uint2*)(g_Blo + (size_t)191 * CHP))[t] = make_uint2(0u, 0u);
        if (t < KC) g_cnt[t] = 0;
        for (int j = t; j < 3 * JN; j += 192) ((float*)g_T3)[j] = 0.f;
        return;
    }
    int k = p / MP, m = p % MP;
    int j = m * KC + k;
    const float4* pr = (const float4*)(proto + (size_t)p * CH);
    float4 v = make_float4(0, 0, 0, 0);
    float ss = 0.f;
    if (t < 180) {
        v = pr[t];
        ss = v.x * v.x + v.y * v.y + v.z * v.z + v.w * v.w;
    }
    ss = blockReduceSum(ss, sh);
    float inv = 1.f / fmaxf(sqrtf(ss), 1e-12f);
    uint2 h = make_uint2(0u, 0u), l = make_uint2(0u, 0u);
    if (t < 180) {
        split2p(v.x * inv, v.y * inv, h.x, l.x);
        split2p(v.z * inv, v.w * inv, h.y, l.y);
    }
    ((uint2*)(g_Bhi + (size_t)j * CHP))[t] = h;
    ((uint2*)(g_Blo + (size_t)j * CHP))[t] = l;
}

// ---------------- K2: HMMA GEMM 64x192, 2 CTAs/SM ----------------
// 256 threads = 8 warps = 2M x 4N, warp tile 32x48. K chunks of 64, 12 chunks.
// SMEM: A hi 8K @0, A lo 8K @8192 (single stage);
//       B stages s=0,1 @ 16384 + s*49152: Bhi 24K, Blo 24K.  Total 114688.
#define GEMM_SMEM 114688

__global__ __launch_bounds__(256, 2) void kgemm_mma(const float* __restrict__ x,
                                                    const float* __restrict__ gamma,
                                                    const float* __restrict__ beta,
                                                    float* __restrict__ sim, int N) {
    extern __shared__ char smem[];
    const uint32_t sb = smem_u32(smem);
    const uint32_t sAhi = sb, sAlo = sb + 8192;

    int tid = threadIdx.x;
    int lane = tid & 31, warp = tid >> 5;
    int wm = warp & 1, wn = warp >> 1;
    int rowBase = (int)blockIdx.x * 64;

    int arow = tid >> 2, aq = tid & 3;      // A: row arow, float4 quads aq+4i
    int brow = tid >> 3, bq = tid & 7;      // B: rows brow + r*32 (r<6), uint4 col bq

    int grow = rowBase + arow;
    bool rowin = grow < N;
    int srow = rowin ? grow : 0;
    float mu = g_mu[srow], Pv = g_P[srow], Qv = g_Q[srow];
    if (!rowin) { mu = 0.f; Pv = 0.f; Qv = 0.f; }
    const float4* xrow = (const float4*)(x + (size_t)srow * CH);

    float acc[2][6][4];
    #pragma unroll
    for (int t = 0; t < 2; t++)
        #pragma unroll
        for (int nt = 0; nt < 6; nt++)
            #pragma unroll
            for (int i = 0; i < 4; i++) acc[t][nt][i] = 0.f;

    float4 xr[4];

    // ---- prologue: xr(0); cp B(0), B(1) ----
    #pragma unroll
    for (int i = 0; i < 4; i++) {
        int qi = aq + 4 * i;
        xr[i] = (rowin && qi < 180) ? xrow[qi] : make_float4(0, 0, 0, 0);
    }
    #pragma unroll
    for (int c = 0; c < 2; c++) {
        uint32_t stB = sb + 16384 + (uint32_t)c * 49152;
        #pragma unroll
        for (int r = 0; r < 6; r++) {
            int row = brow + r * 32;
            uint32_t off = (uint32_t)(row * 128 + ((bq * 16) ^ ((row & 7) << 4)));
            CP_ASYNC16(stB + off, (const char*)(g_Bhi + (size_t)row * CHP + c * 64) + bq * 16);
            CP_ASYNC16(stB + 24576 + off, (const char*)(g_Blo + (size_t)row * CHP + c * 64) + bq * 16);
        }
        asm volatile("cp.async.commit_group;" ::: "memory");
    }

    for (int c = 0; c < 12; c++) {
        // ---- convert + store A(c) (A stage free: sync2 of prev iter) ----
        #pragma unroll
        for (int i = 0; i < 4; i++) {
            int qi = aq + 4 * i;
            int gq = c * 16 + qi;
            float4 g4 = (gq < 180) ? ((const float4*)gamma)[gq] : make_float4(0, 0, 0, 0);
            float4 b4 = (gq < 180) ? ((const float4*)beta)[gq]  : make_float4(0, 0, 0, 0);
            float yx = (xr[i].x - mu) * Pv * g4.x + Qv * b4.x;
            float yy = (xr[i].y - mu) * Pv * g4.y + Qv * b4.y;
            float yz = (xr[i].z - mu) * Pv * g4.z + Qv * b4.z;
            float yw = (xr[i].w - mu) * Pv * g4.w + Qv * b4.w;
            unsigned h0, l0, h1, l1;
            split2p(yx, yy, h0, l0);
            split2p(yz, yw, h1, l1);
            uint32_t off = (uint32_t)(arow * 128 + ((qi * 8) ^ ((arow & 7) << 4)));
            asm volatile("st.shared.v2.b32 [%0], {%1,%2};" :: "r"(sAhi + off), "r"(h0), "r"(h1));
            asm volatile("st.shared.v2.b32 [%0], {%1,%2};" :: "r"(sAlo + off), "r"(l0), "r"(l1));
        }
        asm volatile("cp.async.wait_group 1;" ::: "memory");  // B(c) resident
        __syncthreads();

        // ---- prefetch xr(c+1) (global latency hidden under MMA) ----
        if (c < 11) {
            int c1 = (c + 1) * 16;
            #pragma unroll
            for (int i = 0; i < 4; i++) {
                int qi = aq + 4 * i;
                xr[i] = (rowin && (c1 + qi) < 180) ? xrow[c1 + qi] : make_float4(0, 0, 0, 0);
            }
        }

        // ---- MMA on B stage c&1 ----
        uint32_t stB = sb + 16384 + (uint32_t)(c & 1) * 49152;
        uint32_t sBhi = stB, sBlo = stB + 24576;
        #pragma unroll
        for (int s = 0; s < 4; s++) {
            uint32_t ahi[2][4], alo[2][4], bhi[3][4], blo[3][4];
            uint32_t kb = (uint32_t)(s * 32 + ((lane >> 4) & 1) * 16);
            #pragma unroll
            for (int t = 0; t < 2; t++) {
                int row = wm * 32 + t * 16 + (lane & 15);
                uint32_t off = (uint32_t)(row * 128) + (kb ^ ((uint32_t)(row & 7) << 4));
                LDMX4(ahi[t][0], ahi[t][1], ahi[t][2], ahi[t][3], sAhi + off);
                LDMX4(alo[t][0], alo[t][1], alo[t][2], alo[t][3], sAlo + off);
            }
            #pragma unroll
            for (int g = 0; g < 3; g++) {
                int row = wn * 48 + g * 16 + (lane & 15);
                uint32_t off = (uint32_t)(row * 128) + (kb ^ ((uint32_t)(row & 7) << 4));
                LDMX4(bhi[g][0], bhi[g][1], bhi[g][2], bhi[g][3], sBhi + off);
                LDMX4(blo[g][0], blo[g][1], blo[g][2], blo[g][3], sBlo + off);
            }
            #pragma unroll
            for (int t = 0; t < 2; t++)
                #pragma unroll
                for (int g = 0; g < 3; g++)
                    #pragma unroll
                    for (int h = 0; h < 2; h++) {
                        int nt = g * 2 + h;
                        MMA16816(acc[t][nt], ahi[t], bhi[g][h], bhi[g][h + 2]);
                        MMA16816(acc[t][nt], alo[t], bhi[g][h], bhi[g][h + 2]);
                        MMA16816(acc[t][nt], ahi[t], blo[g][h], blo[g][h + 2]);
                    }
        }
        __syncthreads();   // all warps done with A(c) and B stage c&1

        // ---- cp B(c+2) into stage c&1 (now safe) ----
        if (c < 10) {
            int c2 = (c + 2) * 64;
            uint32_t nB = sb + 16384 + (uint32_t)(c & 1) * 49152;
            #pragma unroll
            for (int r = 0; r < 6; r++) {
                int row = brow + r * 32;
                uint32_t off = (uint32_t)(row * 128 + ((bq * 16) ^ ((row & 7) << 4)));
                CP_ASYNC16(nB + off, (const char*)(g_Bhi + (size_t)row * CHP + c2) + bq * 16);
                CP_ASYNC16(nB + 24576 + off, (const char*)(g_Blo + (size_t)row * CHP + c2) + bq * 16);
            }
        }
        asm volatile("cp.async.commit_group;" ::: "memory");  // keep group count uniform
    }

    // ---- epilogue ----
    #pragma unroll
    for (int t = 0; t < 2; t++) {
        int r0 = rowBase + wm * 32 + t * 16 + (lane >> 2);
        #pragma unroll
        for (int nt = 0; nt < 6; nt++) {
            int cc = wn * 48 + nt * 8 + ((lane & 3) << 1);
            if (cc < JN) {
                if (r0 < N)
                    *(float2*)(sim + (size_t)r0 * JN + cc) =
                        make_float2(acc[t][nt][0], acc[t][nt][1]);
                if (r0 + 8 < N)
                    *(float2*)(sim + (size_t)(r0 + 8) * JN + cc) =
                        make_float2(acc[t][nt][2], acc[t][nt][3]);
            }
        }
    }
}

// ---------------- K3: kpix + E/cnt accumulation ----------------
#define KPIX_SMEM (64 * JN * 4)
__global__ __launch_bounds__(128) void kpix(const float* __restrict__ sim,
                                            const int* __restrict__ gt,
                                            float* __restrict__ pred_out, int N) {
    extern __shared__ float srow[];   // [64][190]
    __shared__ float sE[JN];
    __shared__ int sC[KC];
    for (int j = threadIdx.x; j < JN; j += 128) sE[j] = 0.f;
    if (threadIdx.x < KC) sC[threadIdx.x] = 0;
    int base = blockIdx.x * 64;
    int npix = min(64, N - base);
    if (npix <= 0) return;
    int n4 = npix * JN / 2;
    const float2* src = (const float2*)(sim + (size_t)base * JN);
    float2* dst = (float2*)srow;
    for (int i = threadIdx.x; i < n4; i += 128) dst[i] = src[i];
    __syncthreads();
    if (threadIdx.x < npix) {
        int n = base + threadIdx.x;
        const float* row = srow + threadIdx.x * JN;
        int g = gt[n];
        float best = -3.4e38f; int bk = 0;
        #pragma unroll
        for (int k = 0; k < KC; k++) {
            float mk = row[k];
            #pragma unroll
            for (int m = 1; m < MP; m++) mk = fmaxf(mk, row[m * KC + k]);
            if (mk > best) { best = mk; bk = k; }
        }
        pred_out[n] = (float)bk;
        #pragma unroll
        for (int m = 0; m < MP; m++) {
            float e = expf(row[m * KC + g] * 20.0f);
            g_e[(size_t)n * MP + m] = e;
            atomicAdd(&sE[m * KC + g], e);
        }
        atomicAdd(&sC[g], 1);
    }
    __syncthreads();
    for (int j = threadIdx.x; j < JN; j += 128)
        if (sE[j] != 0.f) atomicAdd(&g_T3[0][j], sE[j]);
    if (threadIdx.x < KC && sC[threadIdx.x] != 0)
        atomicAdd(&g_cnt[threadIdx.x], sC[threadIdx.x]);
}

// ---------------- fused sinkhorn passes ----------------
// r-chain prologue: computes sr[j] = r_{IT} and sS[k] = clip(S)
template<int IT>
__device__ __forceinline__ void r_chain(float* sr, float* sS) {
    int t = threadIdx.x;
    if (t < KC) {
        float s = 0.f;
        #pragma unroll
        for (int m = 0; m < MP; m++) s += g_T3[0][m * KC + t];
        sS[t] = fmaxf(s, 1e-12f);
    }
    __syncthreads();
    if (t < JN) {
        float T0 = g_T3[0][t] / sS[t % KC];
        float r = 1.f / (fmaxf(T0, 1e-12f) * (float)MP);
        #pragma unroll
        for (int it = 1; it < IT; it++)
            r = r / (fmaxf(r * g_T3[it][t], 1e-12f) * (float)MP);
        sr[t] = r;
    }
    __syncthreads();
}

// IT = which r is current (1 or 2). Computes c_IT, stores to g_c, accumulates T3[IT].
template<int IT>
__global__ __launch_bounds__(256) void kCT(const int* __restrict__ gt, int N) {
    __shared__ float sr[JN];
    __shared__ float sS[KC];
    __shared__ float sT[JN];
    r_chain<IT>(sr, sS);
    for (int j = threadIdx.x; j < JN; j += 256) sT[j] = 0.f;
    __syncthreads();
    int n = blockIdx.x * blockDim.x + threadIdx.x;
    if (n < N) {
        int g = gt[n];
        float cprev = (IT == 1) ? (1.f / sS[g]) : g_c[n];
        float e[MP], V = 0.f;
        #pragma unroll
        for (int m = 0; m < MP; m++) { e[m] = g_e[(size_t)n * MP + m]; V += e[m] * sr[g * MP + m]; }
        float ns = fmaxf((float)g_cnt[g], 1.f);
        float c = cprev / (fmaxf(cprev * V, 1e-12f) * ns);
        g_c[n] = c;
        #pragma unroll
        for (int m = 0; m < MP; m++) atomicAdd(&sT[g * MP + m], c * e[m]);
    }
    __syncthreads();
    for (int j = threadIdx.x; j < JN; j += 256)
        if (sT[j] != 0.f) atomicAdd(&g_T3[IT][j], sT[j]);
}

// final: r_3, c_3, write q
__global__ __launch_bounds__(256) void kCQ(const int* __restrict__ gt,
                                           float* __restrict__ qout, int N) {
    __shared__ float sr[JN];
    __shared__ float sS[KC];
    r_chain<3>(sr, sS);
    int n = blockIdx.x * blockDim.x + threadIdx.x;
    if (n >= N) return;
    int g = gt[n];
    float cprev = g_c[n];
    float e[MP], V = 0.f;
    #pragma unroll
    for (int m = 0; m < MP; m++) { e[m] = g_e[(size_t)n * MP + m]; V += e[m] * sr[g * MP + m]; }
    float ns = fmaxf((float)g_cnt[g], 1.f);
    float c = cprev / (fmaxf(cprev * V, 1e-12f) * ns);
    float cs = c * ns;
    size_t base = ((size_t)g * N + n) * MP;
    #pragma unroll
    for (int m = 0; m < MP; m++)
        qout[base + m] = cs * e[m] * sr[g * MP + m];
}

// ---------------- launch ----------------
extern "C" void kernel_launch(void* const* d_in, const int* in_sizes, int n_in,
                              void* d_out, int out_size) {
    const float* x     = (const float*)d_in[0];
    const int*   gt    = (const int*)d_in[1];
    const float* gamma = (const float*)d_in[2];
    const float* beta  = (const float*)d_in[3];
    const float* proto = (const float*)d_in[4];
    int N = in_sizes[0] / CH;

    float* out  = (float*)d_out;
    float* sim  = out;
    float* q    = out + (size_t)N * JN;
    float* pred = out + 2 * (size_t)N * JN;

    cudaFuncSetAttribute(kgemm_mma, cudaFuncAttributeMaxDynamicSharedMemorySize, GEMM_SMEM);
    cudaFuncSetAttribute(kpix, cudaFuncAttributeMaxDynamicSharedMemorySize, KPIX_SMEM);

    kprotoB<<<JN + 1, 192>>>(proto);
    kstats<<<(N + 7) / 8, 256>>>(x, gamma, beta, N);
    kgemm_mma<<<(N + 63) / 64, 256, GEMM_SMEM>>>(x, gamma, beta, sim, N);
    kpix<<<(N + 63) / 64, 128, KPIX_SMEM>>>(sim, gt, pred, N);

    kCT<1><<<(N + 255) / 256, 256>>>(gt, N);
    kCT<2><<<(N + 255) / 256, 256>>>(gt, N);
    cudaMemsetAsync(q, 0, (size_t)N * JN * sizeof(float));
    kCQ<<<(N + 255) / 256, 256>>>(gt, q, N);
}